// round 7
// baseline (speedup 1.0000x reference)
#include <cuda_runtime.h>
#include <stdint.h>

// Problem constants (fixed by the reference setup)
#define Bn 16
#define Pn 784
#define Dn 10000
#define Ln 1000
#define Cn 10

#define WSTRIDE 320   // padded words per row (320*32 = 10240 >= 10000)
#define NSLAB   10    // 10 slabs of 32 words each
#define NCTA    (8 * NSLAB)   // 80 CTAs (batch-pair x slab)

// Scratch (allocation-free: device globals)
__device__ uint32_t g_vbits[Ln * WSTRIDE];   // sign bits of value_weight
__device__ uint32_t g_pbits[Pn * WSTRIDE];   // sign bits of position_weight
__device__ int      g_idx[Bn * Pn];          // level index per (b, pixel)
__device__ float    g_partial[NSLAB * Bn * Cn];
__device__ int      g_ctr;                   // last-CTA counter (reset each run)

// ---------------------------------------------------------------------------
// Kernel 1: compute idx, pack sign bits of both bipolar tables.
// Permuted bit layout: word w, bit l  <->  dim d = (w>>2)*128 + l*4 + (w&3).
// Warp-task = 512 dims: 4 lane-contiguous float4 loads (fully coalesced),
// sign extraction via FSETP feeding VOTE directly, 16 ballots -> 16 words.
// ---------------------------------------------------------------------------
__global__ void __launch_bounds__(256) pack_kernel(const float* __restrict__ x,
                                                   const float* __restrict__ posw,
                                                   const float* __restrict__ valw)
{
    const int tid     = blockIdx.x * blockDim.x + threadIdx.x;
    const int nthread = gridDim.x * blockDim.x;

    if (tid == 0) g_ctr = 0;   // reset fused-finalize counter for this replay

    // level index: idx = clamp(rint(x*999), 0, 999)  (rintf = half-to-even)
    for (int i = tid; i < Bn * Pn; i += nthread) {
        int q = (int)rintf(x[i] * 999.0f);
        g_idx[i] = min(max(q, 0), Ln - 1);
    }

    const int lane   = threadIdx.x & 31;
    const int warpId = tid >> 5;
    const int nWarps = nthread >> 5;
    const int totalTasks = (Ln + Pn) * 20;   // 20 x 512-dim tasks per row

    for (int task = warpId; task < totalTasks; task += nWarps) {
        int row = task / 20;
        int s   = task - row * 20;
        const float* src;
        uint32_t* dst;
        if (row < Ln) {
            src = valw + (size_t)row * Dn;
            dst = g_vbits + row * WSTRIDE;
        } else {
            src = posw + (size_t)(row - Ln) * Dn;
            dst = g_pbits + (row - Ln) * WSTRIDE;
        }

        uint32_t myword = 0;
        if (s < 19) {
            float4 v0 = *reinterpret_cast<const float4*>(src + s * 512 +   0 + lane * 4);
            float4 v1 = *reinterpret_cast<const float4*>(src + s * 512 + 128 + lane * 4);
            float4 v2 = *reinterpret_cast<const float4*>(src + s * 512 + 256 + lane * 4);
            float4 v3 = *reinterpret_cast<const float4*>(src + s * 512 + 384 + lane * 4);
#define PK(sub, vv)                                                          \
            {                                                                \
                uint32_t b0 = __ballot_sync(0xffffffffu, (vv).x < 0.0f);     \
                uint32_t b1 = __ballot_sync(0xffffffffu, (vv).y < 0.0f);     \
                uint32_t b2 = __ballot_sync(0xffffffffu, (vv).z < 0.0f);     \
                uint32_t b3 = __ballot_sync(0xffffffffu, (vv).w < 0.0f);     \
                if (lane == (sub)*4 + 0) myword = b0;                        \
                if (lane == (sub)*4 + 1) myword = b1;                        \
                if (lane == (sub)*4 + 2) myword = b2;                        \
                if (lane == (sub)*4 + 3) myword = b3;                        \
            }
            PK(0, v0) PK(1, v1) PK(2, v2) PK(3, v3)
#undef PK
        } else {
            // tail task (dims 9728..10239): per-lane validity
#pragma unroll
            for (int sub = 0; sub < 4; sub++) {
                int d0 = s * 512 + sub * 128 + lane * 4;
                bool valid = d0 < Dn;            // Dn % 4 == 0
                float4 v = make_float4(0.f, 0.f, 0.f, 0.f);
                if (valid) v = *reinterpret_cast<const float4*>(src + d0);
                uint32_t b0 = __ballot_sync(0xffffffffu, valid && v.x < 0.0f);
                uint32_t b1 = __ballot_sync(0xffffffffu, valid && v.y < 0.0f);
                uint32_t b2 = __ballot_sync(0xffffffffu, valid && v.z < 0.0f);
                uint32_t b3 = __ballot_sync(0xffffffffu, valid && v.w < 0.0f);
                if (lane == sub * 4 + 0) myword = b0;
                if (lane == sub * 4 + 1) myword = b1;
                if (lane == sub * 4 + 2) myword = b2;
                if (lane == sub * 4 + 3) myword = b3;
            }
        }
        if (lane < 16) dst[s * 16 + lane] = myword;      // coalesced 64B
    }
}

// ---------------------------------------------------------------------------
__device__ __forceinline__ void fadd(uint32_t a, uint32_t b, uint32_t cin,
                                     uint32_t& s, uint32_t& cout)
{
    uint32_t t = a ^ b;
    s    = t ^ cin;
    cout = (a & b) | (cin & t);
}

// ---------------------------------------------------------------------------
// Kernel 2: CTA = (batch-pair, slab), 1024 threads = 2 groups x 16 warps.
// Group bsel handles batch b = bp*2+bsel; warp wsub covers 49 pixels.
// Lane = word within slab -> all bit-table loads 128B coalesced.
// Pipelined 7:3 CSA mainloop; PARALLEL 4-round tree reduction across warps;
// threshold; coalesced classify (warp per class, shfl enc broadcast);
// fused last-CTA finalize. Fixed-order reductions, no float atomics.
// ---------------------------------------------------------------------------
__global__ void __launch_bounds__(1024) hdc_main_kernel(const float* __restrict__ cw,
                                                        float* __restrict__ out)
{
    const int bp   = blockIdx.x / NSLAB;         // batch pair 0..7
    const int slab = blockIdx.x - bp * NSLAB;
    const int tid  = threadIdx.x;
    const int lane = tid & 31;
    const int warp = tid >> 5;                   // 0..31
    const int bsel = warp >> 4;                  // 0/1
    const int wsub = warp & 15;                  // 0..15
    const int b    = bp * 2 + bsel;

    __shared__ int      sIdx[2][Pn];
    __shared__ uint32_t buf[2][8][10][33];       // tree-reduction buffer
    __shared__ uint32_t encW[2][32];
    __shared__ int      sLast;

    {   // each 512-thread half loads its own batch's indices
        const int half = tid >> 9;               // == bsel
        const int t2   = tid & 511;
        for (int i = t2; i < Pn; i += 512)
            sIdx[half][i] = g_idx[(bp * 2 + half) * Pn + i];
    }
    __syncthreads();

    const int w = slab * 32 + lane;

    uint32_t a[10];
#pragma unroll
    for (int j = 0; j < 10; j++) a[j] = 0u;

    const int p0 = wsub * 49;
    const uint32_t* __restrict__ vb = g_vbits + w;
    const uint32_t* __restrict__ pb = g_pbits + w;
    const int* __restrict__ sIdx2 = sIdx[bsel];

    // prologue: load group 0
    uint32_t t[7];
#pragma unroll
    for (int k = 0; k < 7; k++) {
        int lvl = sIdx2[p0 + k];
        t[k] = __ldg(vb + lvl * WSTRIDE) ^ __ldg(pb + (p0 + k) * WSTRIDE);
    }

    for (int g = 0; g < 7; g++) {
        uint32_t tn[7];
        if (g < 6) {                             // prefetch next group
            const int pn = p0 + (g + 1) * 7;
#pragma unroll
            for (int k = 0; k < 7; k++) {
                int lvl = sIdx2[pn + k];
                tn[k] = __ldg(vb + lvl * WSTRIDE) ^ __ldg(pb + (pn + k) * WSTRIDE);
            }
        }
        // 7:3 compressor -> (s3, s4, c4) with weights 1,2,4
        uint32_t s1, c1, s2, c2, s3, c3, s4, c4;
        fadd(t[0], t[1], t[2], s1, c1);
        fadd(t[3], t[4], t[5], s2, c2);
        fadd(s1,  s2,  t[6],  s3, c3);
        fadd(c1,  c2,  c3,    s4, c4);
        // merge 3-bit value into the 7-plane counter (planes a[0..6])
        uint32_t carry = a[0] & s3; a[0] ^= s3;
        uint32_t s, co;
        fadd(a[1], s4, carry, s, co); a[1] = s; carry = co;
        fadd(a[2], c4, carry, s, co); a[2] = s; carry = co;
#pragma unroll
        for (int j = 3; j < 7; j++) { uint32_t nc = a[j] ^ carry; carry &= a[j]; a[j] = nc; }
#pragma unroll
        for (int k = 0; k < 7; k++) t[k] = tn[k];
    }

    // ---- parallel tree reduction across the 16 warps of each group ----
#pragma unroll
    for (int r = 0; r < 4; r++) {
        const int half = 8 >> r;                 // 8,4,2,1 readers
        const int np   = 7 + r;                  // planes valid in sources
        if (wsub >= half && wsub < 2 * half) {
#pragma unroll
            for (int j = 0; j < 10; j++)
                if (j < np) buf[bsel][wsub - half][j][lane] = a[j];
        }
        __syncthreads();
        if (wsub < half) {
            uint32_t carry = 0u;
#pragma unroll
            for (int j = 0; j < 10; j++) {
                if (j < np) {
                    uint32_t s, co;
                    fadd(a[j], buf[bsel][wsub][j][lane], carry, s, co);
                    a[j] = s; carry = co;
                } else {
                    uint32_t nc = a[j] ^ carry; carry &= a[j]; a[j] = nc;
                }
            }
        }
        __syncthreads();                         // buffer reused next round
    }

    if (wsub == 0) {
        // enc = +1 iff count < 392 (392 = 0b0110001000)
        uint32_t eq = ~0u, lt = 0u;
        eq &= ~a[9];
        lt |= eq & ~a[8]; eq &= a[8];
        lt |= eq & ~a[7]; eq &= a[7];
        eq &= ~a[6]; eq &= ~a[5]; eq &= ~a[4];
        lt |= eq & ~a[3];
        encW[bsel][lane] = lt;                   // bit set -> enc = +1
    }
    __syncthreads();

    // ---- coalesced classify: warp wsub (<10) handles class wsub, batch b.
    // float4 at dims [d0, d0+3] (d0 = slab*1024 + i*128 + lane*4) maps to
    // bit lane of words i*4+{0..3}; get words via shfl.
    if (wsub < Cn) {
        const uint32_t encReg = encW[bsel][lane];
        const float* __restrict__ wrow = cw + wsub * Dn + slab * 1024;
        float acc = 0.0f;
#pragma unroll
        for (int i = 0; i < 8; i++) {
            uint32_t w0 = __shfl_sync(0xffffffffu, encReg, i * 4 + 0);
            uint32_t w1 = __shfl_sync(0xffffffffu, encReg, i * 4 + 1);
            uint32_t w2 = __shfl_sync(0xffffffffu, encReg, i * 4 + 2);
            uint32_t w3 = __shfl_sync(0xffffffffu, encReg, i * 4 + 3);
            int d0 = slab * 1024 + i * 128 + lane * 4;
            if (d0 < Dn) {                       // Dn%4==0 -> whole float4 valid
                float4 v = *reinterpret_cast<const float4*>(wrow + i * 128 + lane * 4);
                acc += ((w0 >> lane) & 1u) ? v.x : -v.x;
                acc += ((w1 >> lane) & 1u) ? v.y : -v.y;
                acc += ((w2 >> lane) & 1u) ? v.z : -v.z;
                acc += ((w3 >> lane) & 1u) ? v.w : -v.w;
            }
        }
        // deterministic fixed-order warp reduction
#pragma unroll
        for (int off = 16; off >= 1; off >>= 1)
            acc += __shfl_xor_sync(0xffffffffu, acc, off);
        if (lane == 0) g_partial[(slab * Bn + b) * Cn + wsub] = acc;
    }

    // ---- fused finalize: last CTA reduces g_partial and writes out ----
    __syncthreads();
    if (tid == 0) {
        __threadfence();                         // publish g_partial writes
        int prev = atomicAdd(&g_ctr, 1);
        sLast = (prev == NCTA - 1);
    }
    __syncthreads();
    if (sLast) {
        __threadfence();                         // acquire all g_partial
        if (tid < Bn * Cn) {
            float s = 0.0f;
#pragma unroll
            for (int sl = 0; sl < NSLAB; sl++) s += g_partial[sl * Bn * Cn + tid];
            out[tid] = s;
        }
        if (tid == 0) g_ctr = 0;                 // reset for next replay
    }
}

// ---------------------------------------------------------------------------
extern "C" void kernel_launch(void* const* d_in, const int* in_sizes, int n_in,
                              void* d_out, int out_size)
{
    const float* x    = (const float*)d_in[0];   // [16,28,28]
    const float* posw = (const float*)d_in[1];   // [784,10000]
    const float* valw = (const float*)d_in[2];   // [1000,10000]
    const float* cw   = (const float*)d_in[3];   // [10,10000]
    float* out = (float*)d_out;                  // [16,10]

    pack_kernel<<<1184, 256>>>(x, posw, valw);
    hdc_main_kernel<<<NCTA, 1024>>>(cw, out);
}